// round 10
// baseline (speedup 1.0000x reference)
#include <cuda_runtime.h>
#include <math.h>

#define SC 64
#define VC 32
#define DIMF 160
#define NB 64
#define TBL 4096
#define CUTOFF_F 5.0f
#define TILE_N 32       // nodes per finalize block
#define N_MAX 50000

__device__ float g_table[TBL];
__device__ double g_ewsum;
// Scratch accumulator; zero at module load, re-zeroed by k_finalize each run.
__device__ float g_agg[N_MAX * DIMF];

// Warp-per-entry table build: lane l handles basis l and l+32, shuffle-reduce.
// t(d) = sigmoid( cut(d) * sum_b exp(-0.5*((d-c_b)/w_b)^2) * pw_b + pb ).
// Thread 0 zeroes the edge-weight accumulator (runs before k_scatter).
__global__ void k_table(const float* __restrict__ centers,
                        const float* __restrict__ widths,
                        const float* __restrict__ pw,
                        const float* __restrict__ pb) {
    int gt = blockIdx.x * blockDim.x + threadIdx.x;
    if (gt == 0) g_ewsum = 0.0;
    int entry = gt >> 5;
    int lane = gt & 31;
    if (entry >= TBL) return;
    float d = CUTOFF_F * (float)entry / (float)(TBL - 1);
    float z0 = (d - centers[lane]) / widths[lane];
    float z1 = (d - centers[lane + 32]) / widths[lane + 32];
    float v = expf(-0.5f * z0 * z0) * pw[lane] + expf(-0.5f * z1 * z1) * pw[lane + 32];
#pragma unroll
    for (int o = 16; o > 0; o >>= 1) v += __shfl_down_sync(0xffffffffu, v, o);
    if (lane == 0) {
        float cut = 0.5f * (cosf(3.14159265358979323846f * d / CUTOFF_F) + 1.0f);
        float t = v * cut + pb[0];
        g_table[entry] = 1.0f / (1.0f + expf(-t));
    }
}

// Scatter-add raw x[src] rows (40 float4) into g_agg[dst], with the per-edge
// weight computation fused in (warp 0 computes 32 edge weights via table lerp,
// overlapped with the LTS-bound RED traffic of the other warps).
__global__ void k_scatter(const int* __restrict__ ei,
                          const float* __restrict__ x,
                          const float* __restrict__ pos, int E) {
    __shared__ int ss[32], sd[32];
    int base = blockIdx.x * 32;
    int t = threadIdx.x;
    if (t < 32) {
        int e = base + t;
        ss[t] = (e < E) ? ei[e] : 0;
    } else if (t < 64) {
        int e = base + t - 32;
        sd[t - 32] = (e < E) ? ei[E + e] : 0;
    }
    __syncthreads();

    // Fused edge weight (warp 0 only)
    if (t < 32) {
        float v = 0.f;
        int e = base + t;
        if (e < E) {
            int s = ss[t], d = sd[t];
            float dx = pos[3*s+0] - pos[3*d+0];
            float dy = pos[3*s+1] - pos[3*d+1];
            float dz = pos[3*s+2] - pos[3*d+2];
            float dist = sqrtf(dx*dx + dy*dy + dz*dz);
            float u = fminf(dist, CUTOFF_F) * ((float)(TBL - 1) / CUTOFF_F);
            int i0 = (int)u;
            if (i0 > TBL - 2) i0 = TBL - 2;
            float f = u - (float)i0;
            float t0 = g_table[i0];
            float t1 = g_table[i0 + 1];
            v = t0 + f * (t1 - t0);
        }
#pragma unroll
        for (int o = 16; o > 0; o >>= 1) v += __shfl_down_sync(0xffffffffu, v, o);
        if (t == 0) atomicAdd(&g_ewsum, (double)v);
    }

#pragma unroll
    for (int it = 0; it < 5; it++) {
        int j = t + it * 256;          // 0..1279 = 32 edges * 40 float4
        int el = j / 40;
        int k = j - el * 40;
        if (base + el >= E) continue;
        float4 v = *reinterpret_cast<const float4*>(x + (size_t)ss[el] * DIMF + k * 4);
        float* dp = g_agg + (size_t)sd[el] * DIMF + k * 4;
        asm volatile("red.global.add.v4.f32 [%0], {%1, %2, %3, %4};"
                     :: "l"(dp), "f"(v.x), "f"(v.y), "f"(v.z), "f"(v.w)
                     : "memory");
    }
}

// Tiled finalize: 32 nodes/block, W0+W1 in shared, thread (tn=t/8, tc=t%8)
// computes node tn's scalar cols {4tc..+4, 32+4tc..+4} and vector cols
// 64+12tc..+12. Consumes g_agg and re-zeroes it (keeps the scratch clean for
// the next graph replay), writes the final result to out.
__global__ void __launch_bounds__(256, 5) k_finalize(
        float* __restrict__ out,
        const float* __restrict__ W0,
        const float* __restrict__ W1,
        const float* __restrict__ gamma,
        const float* __restrict__ beta,
        int N, int E) {
    __shared__ float sA[TILE_N][164];      // 164-pad: distinct banks per tn
    __shared__ float W0sh[SC][SC];
    __shared__ float W1sh[VC][VC];

    int t  = threadIdx.x;
    int tn = t >> 3;
    int tc = t & 7;
    int base = blockIdx.x * TILE_N;
    int n = base + tn;

    for (int i = t; i < SC * SC; i += 256) W0sh[i >> 6][i & 63] = W0[i];
    for (int i = t; i < VC * VC; i += 256) W1sh[i >> 5][i & 31] = W1[i];

    const float4 z4 = make_float4(0.f, 0.f, 0.f, 0.f);
    for (int j = t; j < TILE_N * (DIMF / 4); j += 256) {
        int r  = j / 40;
        int c4 = j - r * 40;
        float4 v = z4;
        int nr = base + r;
        if (nr < N) {
            float4* ap = reinterpret_cast<float4*>(g_agg + (size_t)nr * DIMF + c4 * 4);
            v = *ap;
            *ap = z4;   // consume-and-rezero: scratch stays clean for next replay
        }
        *reinterpret_cast<float4*>(&sA[r][c4 * 4]) = v;
    }

    float ew  = (float)(g_ewsum / (double)E);
    float ews = ew * 0.125f;
    float ewv = ew * 0.17677669529663689f;
    float4 gl = *reinterpret_cast<const float4*>(gamma + tc * 4);
    float4 gh = *reinterpret_cast<const float4*>(gamma + 32 + tc * 4);
    float4 bl = *reinterpret_cast<const float4*>(beta + tc * 4);
    float4 bh = *reinterpret_cast<const float4*>(beta + 32 + tc * 4);

    __syncthreads();

    // ---- scalar path: 8 accumulators ----
    float as[8];
#pragma unroll
    for (int q = 0; q < 8; q++) as[q] = 0.f;
#pragma unroll
    for (int k = 0; k < SC; k += 4) {
        float4 a4 = *reinterpret_cast<const float4*>(&sA[tn][k]);
        float av[4] = {a4.x, a4.y, a4.z, a4.w};
#pragma unroll
        for (int kk = 0; kk < 4; kk++) {
            float4 wl = *reinterpret_cast<const float4*>(&W0sh[k + kk][tc * 4]);
            float4 wh = *reinterpret_cast<const float4*>(&W0sh[k + kk][32 + tc * 4]);
            float a = av[kk];
            as[0] = fmaf(a, wl.x, as[0]);
            as[1] = fmaf(a, wl.y, as[1]);
            as[2] = fmaf(a, wl.z, as[2]);
            as[3] = fmaf(a, wl.w, as[3]);
            as[4] = fmaf(a, wh.x, as[4]);
            as[5] = fmaf(a, wh.y, as[5]);
            as[6] = fmaf(a, wh.z, as[6]);
            as[7] = fmaf(a, wh.w, as[7]);
        }
    }

    // ---- vector path: 12 accumulators ----
    float avv[12];
#pragma unroll
    for (int q = 0; q < 12; q++) avv[q] = 0.f;
#pragma unroll
    for (int c = 0; c < VC; c++) {
        float a0 = sA[tn][SC + 3 * c + 0];
        float a1 = sA[tn][SC + 3 * c + 1];
        float a2 = sA[tn][SC + 3 * c + 2];
        float4 w = *reinterpret_cast<const float4*>(&W1sh[c][tc * 4]);
        avv[0]  = fmaf(a0, w.x, avv[0]);
        avv[1]  = fmaf(a1, w.x, avv[1]);
        avv[2]  = fmaf(a2, w.x, avv[2]);
        avv[3]  = fmaf(a0, w.y, avv[3]);
        avv[4]  = fmaf(a1, w.y, avv[4]);
        avv[5]  = fmaf(a2, w.y, avv[5]);
        avv[6]  = fmaf(a0, w.z, avv[6]);
        avv[7]  = fmaf(a1, w.z, avv[7]);
        avv[8]  = fmaf(a2, w.z, avv[8]);
        avv[9]  = fmaf(a0, w.w, avv[9]);
        avv[10] = fmaf(a1, w.w, avv[10]);
        avv[11] = fmaf(a2, w.w, avv[11]);
    }

    // ---- scale + LN stats over the 8 lanes sharing this tn ----
    float s1 = 0.f, s2 = 0.f;
#pragma unroll
    for (int q = 0; q < 8; q++) {
        as[q] *= ews;
        s1 += as[q];
        s2 += as[q] * as[q];
    }
#pragma unroll
    for (int o = 1; o < 8; o <<= 1) {
        s1 += __shfl_xor_sync(0xffffffffu, s1, o);
        s2 += __shfl_xor_sync(0xffffffffu, s2, o);
    }
    float mu  = s1 * (1.0f / SC);
    float var = s2 * (1.0f / SC) - mu * mu;
    float rstd = rsqrtf(var + 1e-5f);

    if (n < N) {
        float* orow = out + (size_t)n * DIMF;
        float x0 = (as[0] - mu) * rstd * gl.x + bl.x;
        float x1 = (as[1] - mu) * rstd * gl.y + bl.y;
        float x2 = (as[2] - mu) * rstd * gl.z + bl.z;
        float x3 = (as[3] - mu) * rstd * gl.w + bl.w;
        float4 r0 = make_float4(x0 / (1.f + expf(-x0)), x1 / (1.f + expf(-x1)),
                                x2 / (1.f + expf(-x2)), x3 / (1.f + expf(-x3)));
        float y0 = (as[4] - mu) * rstd * gh.x + bh.x;
        float y1 = (as[5] - mu) * rstd * gh.y + bh.y;
        float y2 = (as[6] - mu) * rstd * gh.z + bh.z;
        float y3 = (as[7] - mu) * rstd * gh.w + bh.w;
        float4 r1 = make_float4(y0 / (1.f + expf(-y0)), y1 / (1.f + expf(-y1)),
                                y2 / (1.f + expf(-y2)), y3 / (1.f + expf(-y3)));
        *reinterpret_cast<float4*>(orow + tc * 4)      = r0;
        *reinterpret_cast<float4*>(orow + 32 + tc * 4) = r1;
        float* ov = orow + SC + tc * 12;
        *reinterpret_cast<float4*>(ov + 0) =
            make_float4(avv[0] * ewv, avv[1] * ewv, avv[2] * ewv, avv[3] * ewv);
        *reinterpret_cast<float4*>(ov + 4) =
            make_float4(avv[4] * ewv, avv[5] * ewv, avv[6] * ewv, avv[7] * ewv);
        *reinterpret_cast<float4*>(ov + 8) =
            make_float4(avv[8] * ewv, avv[9] * ewv, avv[10] * ewv, avv[11] * ewv);
    }
}

extern "C" void kernel_launch(void* const* d_in, const int* in_sizes, int n_in,
                              void* d_out, int out_size) {
    const float* x       = (const float*)d_in[0];
    const float* pos     = (const float*)d_in[1];
    const int*   ei      = (const int*)d_in[2];   // int32 (JAX x64 disabled)
    // d_in[3] = edge_rand: unused (rotation cancels algebraically)
    const float* W0      = (const float*)d_in[4];
    const float* W1      = (const float*)d_in[5];
    const float* centers = (const float*)d_in[6];
    const float* widths  = (const float*)d_in[7];
    const float* pw      = (const float*)d_in[8];
    const float* pb      = (const float*)d_in[9];
    const float* gamma   = (const float*)d_in[10];
    const float* beta    = (const float*)d_in[11];
    float* out = (float*)d_out;

    int N = in_sizes[0] / DIMF;
    int E = in_sizes[2] / 2;

    k_table<<<(TBL * 32) / 256, 256>>>(centers, widths, pw, pb);
    k_scatter<<<(E + 31) / 32, 256>>>(ei, x, pos, E);
    k_finalize<<<(N + TILE_N - 1) / TILE_N, 256>>>(out, W0, W1, gamma, beta, N, E);
}

// round 11
// speedup vs baseline: 1.3084x; 1.3084x over previous
#include <cuda_runtime.h>
#include <math.h>

#define SC 64
#define VC 32
#define DIMF 160
#define NB 64
#define TBL 4096
#define CUTOFF_F 5.0f
#define TILE_N 32       // nodes per finalize block

__device__ float g_table[TBL];
__device__ double g_ewsum;

// Fused: warp-per-entry table build + grid-stride zeroing of the output
// accumulator (replaces the separate cudaMemsetAsync node).
// Table: lane l handles basis l and l+32, shuffle-reduce.
// t(d) = sigmoid( cut(d) * sum_b exp(-0.5*((d-c_b)/w_b)^2) * pw_b + pb ).
__global__ void k_table_zero(const float* __restrict__ centers,
                             const float* __restrict__ widths,
                             const float* __restrict__ pw,
                             const float* __restrict__ pb,
                             float4* __restrict__ outz, int nq) {
    int gt = blockIdx.x * blockDim.x + threadIdx.x;
    if (gt == 0) g_ewsum = 0.0;

    int entry = gt >> 5;
    int lane = gt & 31;
    if (entry < TBL) {
        float d = CUTOFF_F * (float)entry / (float)(TBL - 1);
        float z0 = (d - centers[lane]) / widths[lane];
        float z1 = (d - centers[lane + 32]) / widths[lane + 32];
        float v = expf(-0.5f * z0 * z0) * pw[lane]
                + expf(-0.5f * z1 * z1) * pw[lane + 32];
#pragma unroll
        for (int o = 16; o > 0; o >>= 1) v += __shfl_down_sync(0xffffffffu, v, o);
        if (lane == 0) {
            float cut = 0.5f * (cosf(3.14159265358979323846f * d / CUTOFF_F) + 1.0f);
            float t = v * cut + pb[0];
            g_table[entry] = 1.0f / (1.0f + expf(-t));
        }
    }

    // Zero the accumulator (32 MB), overlapped with the table math above.
    const float4 z4 = make_float4(0.f, 0.f, 0.f, 0.f);
    int stride = gridDim.x * blockDim.x;
    for (int i = gt; i < nq; i += stride) outz[i] = z4;
}

// Scatter-add raw x[src] rows (40 float4) into out[dst], with the per-edge
// weight computation fused in (warp 0 computes 32 edge weights via table lerp,
// overlapped with the LTS-bound RED traffic of the other warps).
__global__ void k_scatter(const int* __restrict__ ei,
                          const float* __restrict__ x,
                          const float* __restrict__ pos,
                          float* __restrict__ out, int E) {
    __shared__ int ss[32], sd[32];
    int base = blockIdx.x * 32;
    int t = threadIdx.x;
    if (t < 32) {
        int e = base + t;
        ss[t] = (e < E) ? ei[e] : 0;
    } else if (t < 64) {
        int e = base + t - 32;
        sd[t - 32] = (e < E) ? ei[E + e] : 0;
    }
    __syncthreads();

    // Fused edge weight (warp 0 only)
    if (t < 32) {
        float v = 0.f;
        int e = base + t;
        if (e < E) {
            int s = ss[t], d = sd[t];
            float dx = pos[3*s+0] - pos[3*d+0];
            float dy = pos[3*s+1] - pos[3*d+1];
            float dz = pos[3*s+2] - pos[3*d+2];
            float dist = sqrtf(dx*dx + dy*dy + dz*dz);
            float u = fminf(dist, CUTOFF_F) * ((float)(TBL - 1) / CUTOFF_F);
            int i0 = (int)u;
            if (i0 > TBL - 2) i0 = TBL - 2;
            float f = u - (float)i0;
            float t0 = g_table[i0];
            float t1 = g_table[i0 + 1];
            v = t0 + f * (t1 - t0);
        }
#pragma unroll
        for (int o = 16; o > 0; o >>= 1) v += __shfl_down_sync(0xffffffffu, v, o);
        if (t == 0) atomicAdd(&g_ewsum, (double)v);
    }

#pragma unroll
    for (int it = 0; it < 5; it++) {
        int j = t + it * 256;          // 0..1279 = 32 edges * 40 float4
        int el = j / 40;
        int k = j - el * 40;
        if (base + el >= E) continue;
        float4 v = *reinterpret_cast<const float4*>(x + (size_t)ss[el] * DIMF + k * 4);
        float* dp = out + (size_t)sd[el] * DIMF + k * 4;
        asm volatile("red.global.add.v4.f32 [%0], {%1, %2, %3, %4};"
                     :: "l"(dp), "f"(v.x), "f"(v.y), "f"(v.z), "f"(v.w)
                     : "memory");
    }
}

// Tiled finalize: 32 nodes/block, W0+W1 in shared, thread (tn=t/8, tc=t%8)
// computes node tn's scalar cols {4tc..+4, 32+4tc..+4} and vector cols
// 64+12tc..+12. minBlocks=5 forces regs<=51 for 40 warps/SM.
__global__ void __launch_bounds__(256, 5) k_finalize(
        float* __restrict__ out,
        const float* __restrict__ W0,
        const float* __restrict__ W1,
        const float* __restrict__ gamma,
        const float* __restrict__ beta,
        int N, int E) {
    __shared__ float sA[TILE_N][164];      // 164-pad: distinct banks per tn
    __shared__ float W0sh[SC][SC];
    __shared__ float W1sh[VC][VC];

    int t  = threadIdx.x;
    int tn = t >> 3;
    int tc = t & 7;
    int base = blockIdx.x * TILE_N;
    int n = base + tn;

    for (int i = t; i < SC * SC; i += 256) W0sh[i >> 6][i & 63] = W0[i];
    for (int i = t; i < VC * VC; i += 256) W1sh[i >> 5][i & 31] = W1[i];

    for (int j = t; j < TILE_N * (DIMF / 4); j += 256) {
        int r  = j / 40;
        int c4 = j - r * 40;
        float4 v = make_float4(0.f, 0.f, 0.f, 0.f);
        int nr = base + r;
        if (nr < N) v = *reinterpret_cast<const float4*>(out + (size_t)nr * DIMF + c4 * 4);
        *reinterpret_cast<float4*>(&sA[r][c4 * 4]) = v;
    }

    float ew  = (float)(g_ewsum / (double)E);
    float ews = ew * 0.125f;
    float ewv = ew * 0.17677669529663689f;
    float4 gl = *reinterpret_cast<const float4*>(gamma + tc * 4);
    float4 gh = *reinterpret_cast<const float4*>(gamma + 32 + tc * 4);
    float4 bl = *reinterpret_cast<const float4*>(beta + tc * 4);
    float4 bh = *reinterpret_cast<const float4*>(beta + 32 + tc * 4);

    __syncthreads();

    // ---- scalar path: 8 accumulators ----
    float as[8];
#pragma unroll
    for (int q = 0; q < 8; q++) as[q] = 0.f;
#pragma unroll
    for (int k = 0; k < SC; k += 4) {
        float4 a4 = *reinterpret_cast<const float4*>(&sA[tn][k]);
        float av[4] = {a4.x, a4.y, a4.z, a4.w};
#pragma unroll
        for (int kk = 0; kk < 4; kk++) {
            float4 wl = *reinterpret_cast<const float4*>(&W0sh[k + kk][tc * 4]);
            float4 wh = *reinterpret_cast<const float4*>(&W0sh[k + kk][32 + tc * 4]);
            float a = av[kk];
            as[0] = fmaf(a, wl.x, as[0]);
            as[1] = fmaf(a, wl.y, as[1]);
            as[2] = fmaf(a, wl.z, as[2]);
            as[3] = fmaf(a, wl.w, as[3]);
            as[4] = fmaf(a, wh.x, as[4]);
            as[5] = fmaf(a, wh.y, as[5]);
            as[6] = fmaf(a, wh.z, as[6]);
            as[7] = fmaf(a, wh.w, as[7]);
        }
    }

    // ---- vector path: 12 accumulators ----
    float avv[12];
#pragma unroll
    for (int q = 0; q < 12; q++) avv[q] = 0.f;
#pragma unroll
    for (int c = 0; c < VC; c++) {
        float a0 = sA[tn][SC + 3 * c + 0];
        float a1 = sA[tn][SC + 3 * c + 1];
        float a2 = sA[tn][SC + 3 * c + 2];
        float4 w = *reinterpret_cast<const float4*>(&W1sh[c][tc * 4]);
        avv[0]  = fmaf(a0, w.x, avv[0]);
        avv[1]  = fmaf(a1, w.x, avv[1]);
        avv[2]  = fmaf(a2, w.x, avv[2]);
        avv[3]  = fmaf(a0, w.y, avv[3]);
        avv[4]  = fmaf(a1, w.y, avv[4]);
        avv[5]  = fmaf(a2, w.y, avv[5]);
        avv[6]  = fmaf(a0, w.z, avv[6]);
        avv[7]  = fmaf(a1, w.z, avv[7]);
        avv[8]  = fmaf(a2, w.z, avv[8]);
        avv[9]  = fmaf(a0, w.w, avv[9]);
        avv[10] = fmaf(a1, w.w, avv[10]);
        avv[11] = fmaf(a2, w.w, avv[11]);
    }

    // ---- scale + LN stats over the 8 lanes sharing this tn ----
    float s1 = 0.f, s2 = 0.f;
#pragma unroll
    for (int q = 0; q < 8; q++) {
        as[q] *= ews;
        s1 += as[q];
        s2 += as[q] * as[q];
    }
#pragma unroll
    for (int o = 1; o < 8; o <<= 1) {
        s1 += __shfl_xor_sync(0xffffffffu, s1, o);
        s2 += __shfl_xor_sync(0xffffffffu, s2, o);
    }
    float mu  = s1 * (1.0f / SC);
    float var = s2 * (1.0f / SC) - mu * mu;
    float rstd = rsqrtf(var + 1e-5f);

    if (n < N) {
        float* orow = out + (size_t)n * DIMF;
        float x0 = (as[0] - mu) * rstd * gl.x + bl.x;
        float x1 = (as[1] - mu) * rstd * gl.y + bl.y;
        float x2 = (as[2] - mu) * rstd * gl.z + bl.z;
        float x3 = (as[3] - mu) * rstd * gl.w + bl.w;
        float4 r0 = make_float4(x0 / (1.f + expf(-x0)), x1 / (1.f + expf(-x1)),
                                x2 / (1.f + expf(-x2)), x3 / (1.f + expf(-x3)));
        float y0 = (as[4] - mu) * rstd * gh.x + bh.x;
        float y1 = (as[5] - mu) * rstd * gh.y + bh.y;
        float y2 = (as[6] - mu) * rstd * gh.z + bh.z;
        float y3 = (as[7] - mu) * rstd * gh.w + bh.w;
        float4 r1 = make_float4(y0 / (1.f + expf(-y0)), y1 / (1.f + expf(-y1)),
                                y2 / (1.f + expf(-y2)), y3 / (1.f + expf(-y3)));
        *reinterpret_cast<float4*>(orow + tc * 4)      = r0;
        *reinterpret_cast<float4*>(orow + 32 + tc * 4) = r1;
        float* ov = orow + SC + tc * 12;
        *reinterpret_cast<float4*>(ov + 0) =
            make_float4(avv[0] * ewv, avv[1] * ewv, avv[2] * ewv, avv[3] * ewv);
        *reinterpret_cast<float4*>(ov + 4) =
            make_float4(avv[4] * ewv, avv[5] * ewv, avv[6] * ewv, avv[7] * ewv);
        *reinterpret_cast<float4*>(ov + 8) =
            make_float4(avv[8] * ewv, avv[9] * ewv, avv[10] * ewv, avv[11] * ewv);
    }
}

extern "C" void kernel_launch(void* const* d_in, const int* in_sizes, int n_in,
                              void* d_out, int out_size) {
    const float* x       = (const float*)d_in[0];
    const float* pos     = (const float*)d_in[1];
    const int*   ei      = (const int*)d_in[2];   // int32 (JAX x64 disabled)
    // d_in[3] = edge_rand: unused (rotation cancels algebraically)
    const float* W0      = (const float*)d_in[4];
    const float* W1      = (const float*)d_in[5];
    const float* centers = (const float*)d_in[6];
    const float* widths  = (const float*)d_in[7];
    const float* pw      = (const float*)d_in[8];
    const float* pb      = (const float*)d_in[9];
    const float* gamma   = (const float*)d_in[10];
    const float* beta    = (const float*)d_in[11];
    float* out = (float*)d_out;

    int N = in_sizes[0] / DIMF;
    int E = in_sizes[2] / 2;
    int nq = (N * DIMF) / 4;   // float4 count of out

    k_table_zero<<<(TBL * 32) / 256, 256>>>(centers, widths, pw, pb,
                                            (float4*)out, nq);
    k_scatter<<<(E + 31) / 32, 256>>>(ei, x, pos, out, E);
    k_finalize<<<(N + TILE_N - 1) / TILE_N, 256>>>(out, W0, W1, gamma, beta, N, E);
}

// round 12
// speedup vs baseline: 1.3936x; 1.0651x over previous
#include <cuda_runtime.h>
#include <math.h>

#define SC 64
#define VC 32
#define DIMF 160
#define NB 64
#define TBL 4096
#define CUTOFF_F 5.0f
#define TILE_N 32       // nodes per finalize block

__device__ float g_table[TBL];
__device__ double g_ewsum;

// Fused: warp-per-entry table build + grid-stride zeroing of the output
// accumulator. Launched WIDE (2560 blocks) so the 32 MB zeroing runs at
// memset-like parallelism; only the first 512 blocks carry table entries.
__global__ void k_table_zero(const float* __restrict__ centers,
                             const float* __restrict__ widths,
                             const float* __restrict__ pw,
                             const float* __restrict__ pb,
                             float4* __restrict__ outz, int nq) {
    int gt = blockIdx.x * blockDim.x + threadIdx.x;
    if (gt == 0) g_ewsum = 0.0;

    int entry = gt >> 5;
    int lane = gt & 31;
    if (entry < TBL) {
        float d = CUTOFF_F * (float)entry / (float)(TBL - 1);
        float z0 = (d - centers[lane]) / widths[lane];
        float z1 = (d - centers[lane + 32]) / widths[lane + 32];
        float v = expf(-0.5f * z0 * z0) * pw[lane]
                + expf(-0.5f * z1 * z1) * pw[lane + 32];
#pragma unroll
        for (int o = 16; o > 0; o >>= 1) v += __shfl_down_sync(0xffffffffu, v, o);
        if (lane == 0) {
            float cut = 0.5f * (cosf(3.14159265358979323846f * d / CUTOFF_F) + 1.0f);
            float t = v * cut + pb[0];
            g_table[entry] = 1.0f / (1.0f + expf(-t));
        }
    }

    // Zero the 32 MB accumulator with full-chip parallelism.
    const float4 z4 = make_float4(0.f, 0.f, 0.f, 0.f);
    int stride = gridDim.x * blockDim.x;
    for (int i = gt; i < nq; i += stride) outz[i] = z4;
}

// Scatter-add raw x[src] rows (40 float4) into out[dst], with the per-edge
// weight computation fused in (warp 0 computes 32 edge weights via table lerp,
// overlapped with the LTS-bound RED traffic of the other warps).
__global__ void k_scatter(const int* __restrict__ ei,
                          const float* __restrict__ x,
                          const float* __restrict__ pos,
                          float* __restrict__ out, int E) {
    __shared__ int ss[32], sd[32];
    int base = blockIdx.x * 32;
    int t = threadIdx.x;
    if (t < 32) {
        int e = base + t;
        ss[t] = (e < E) ? ei[e] : 0;
    } else if (t < 64) {
        int e = base + t - 32;
        sd[t - 32] = (e < E) ? ei[E + e] : 0;
    }
    __syncthreads();

    // Fused edge weight (warp 0 only)
    if (t < 32) {
        float v = 0.f;
        int e = base + t;
        if (e < E) {
            int s = ss[t], d = sd[t];
            float dx = pos[3*s+0] - pos[3*d+0];
            float dy = pos[3*s+1] - pos[3*d+1];
            float dz = pos[3*s+2] - pos[3*d+2];
            float dist = sqrtf(dx*dx + dy*dy + dz*dz);
            float u = fminf(dist, CUTOFF_F) * ((float)(TBL - 1) / CUTOFF_F);
            int i0 = (int)u;
            if (i0 > TBL - 2) i0 = TBL - 2;
            float f = u - (float)i0;
            float t0 = g_table[i0];
            float t1 = g_table[i0 + 1];
            v = t0 + f * (t1 - t0);
        }
#pragma unroll
        for (int o = 16; o > 0; o >>= 1) v += __shfl_down_sync(0xffffffffu, v, o);
        if (t == 0) atomicAdd(&g_ewsum, (double)v);
    }

#pragma unroll
    for (int it = 0; it < 5; it++) {
        int j = t + it * 256;          // 0..1279 = 32 edges * 40 float4
        int el = j / 40;
        int k = j - el * 40;
        if (base + el >= E) continue;
        float4 v = *reinterpret_cast<const float4*>(x + (size_t)ss[el] * DIMF + k * 4);
        float* dp = out + (size_t)sd[el] * DIMF + k * 4;
        asm volatile("red.global.add.v4.f32 [%0], {%1, %2, %3, %4};"
                     :: "l"(dp), "f"(v.x), "f"(v.y), "f"(v.z), "f"(v.w)
                     : "memory");
    }
}

// Tiled finalize: 32 nodes/block, W0+W1 in shared, thread (tn=t/8, tc=t%8)
// computes node tn's scalar cols {4tc..+4, 32+4tc..+4} and vector cols
// 64+12tc..+12. minBlocks=5 forces regs<=51 for 40 warps/SM.
__global__ void __launch_bounds__(256, 5) k_finalize(
        float* __restrict__ out,
        const float* __restrict__ W0,
        const float* __restrict__ W1,
        const float* __restrict__ gamma,
        const float* __restrict__ beta,
        int N, int E) {
    __shared__ float sA[TILE_N][164];      // 164-pad: distinct banks per tn
    __shared__ float W0sh[SC][SC];
    __shared__ float W1sh[VC][VC];

    int t  = threadIdx.x;
    int tn = t >> 3;
    int tc = t & 7;
    int base = blockIdx.x * TILE_N;
    int n = base + tn;

    for (int i = t; i < SC * SC; i += 256) W0sh[i >> 6][i & 63] = W0[i];
    for (int i = t; i < VC * VC; i += 256) W1sh[i >> 5][i & 31] = W1[i];

    for (int j = t; j < TILE_N * (DIMF / 4); j += 256) {
        int r  = j / 40;
        int c4 = j - r * 40;
        float4 v = make_float4(0.f, 0.f, 0.f, 0.f);
        int nr = base + r;
        if (nr < N) v = *reinterpret_cast<const float4*>(out + (size_t)nr * DIMF + c4 * 4);
        *reinterpret_cast<float4*>(&sA[r][c4 * 4]) = v;
    }

    float ew  = (float)(g_ewsum / (double)E);
    float ews = ew * 0.125f;
    float ewv = ew * 0.17677669529663689f;
    float4 gl = *reinterpret_cast<const float4*>(gamma + tc * 4);
    float4 gh = *reinterpret_cast<const float4*>(gamma + 32 + tc * 4);
    float4 bl = *reinterpret_cast<const float4*>(beta + tc * 4);
    float4 bh = *reinterpret_cast<const float4*>(beta + 32 + tc * 4);

    __syncthreads();

    // ---- scalar path: 8 accumulators ----
    float as[8];
#pragma unroll
    for (int q = 0; q < 8; q++) as[q] = 0.f;
#pragma unroll
    for (int k = 0; k < SC; k += 4) {
        float4 a4 = *reinterpret_cast<const float4*>(&sA[tn][k]);
        float av[4] = {a4.x, a4.y, a4.z, a4.w};
#pragma unroll
        for (int kk = 0; kk < 4; kk++) {
            float4 wl = *reinterpret_cast<const float4*>(&W0sh[k + kk][tc * 4]);
            float4 wh = *reinterpret_cast<const float4*>(&W0sh[k + kk][32 + tc * 4]);
            float a = av[kk];
            as[0] = fmaf(a, wl.x, as[0]);
            as[1] = fmaf(a, wl.y, as[1]);
            as[2] = fmaf(a, wl.z, as[2]);
            as[3] = fmaf(a, wl.w, as[3]);
            as[4] = fmaf(a, wh.x, as[4]);
            as[5] = fmaf(a, wh.y, as[5]);
            as[6] = fmaf(a, wh.z, as[6]);
            as[7] = fmaf(a, wh.w, as[7]);
        }
    }

    // ---- vector path: 12 accumulators ----
    float avv[12];
#pragma unroll
    for (int q = 0; q < 12; q++) avv[q] = 0.f;
#pragma unroll
    for (int c = 0; c < VC; c++) {
        float a0 = sA[tn][SC + 3 * c + 0];
        float a1 = sA[tn][SC + 3 * c + 1];
        float a2 = sA[tn][SC + 3 * c + 2];
        float4 w = *reinterpret_cast<const float4*>(&W1sh[c][tc * 4]);
        avv[0]  = fmaf(a0, w.x, avv[0]);
        avv[1]  = fmaf(a1, w.x, avv[1]);
        avv[2]  = fmaf(a2, w.x, avv[2]);
        avv[3]  = fmaf(a0, w.y, avv[3]);
        avv[4]  = fmaf(a1, w.y, avv[4]);
        avv[5]  = fmaf(a2, w.y, avv[5]);
        avv[6]  = fmaf(a0, w.z, avv[6]);
        avv[7]  = fmaf(a1, w.z, avv[7]);
        avv[8]  = fmaf(a2, w.z, avv[8]);
        avv[9]  = fmaf(a0, w.w, avv[9]);
        avv[10] = fmaf(a1, w.w, avv[10]);
        avv[11] = fmaf(a2, w.w, avv[11]);
    }

    // ---- scale + LN stats over the 8 lanes sharing this tn ----
    float s1 = 0.f, s2 = 0.f;
#pragma unroll
    for (int q = 0; q < 8; q++) {
        as[q] *= ews;
        s1 += as[q];
        s2 += as[q] * as[q];
    }
#pragma unroll
    for (int o = 1; o < 8; o <<= 1) {
        s1 += __shfl_xor_sync(0xffffffffu, s1, o);
        s2 += __shfl_xor_sync(0xffffffffu, s2, o);
    }
    float mu  = s1 * (1.0f / SC);
    float var = s2 * (1.0f / SC) - mu * mu;
    float rstd = rsqrtf(var + 1e-5f);

    if (n < N) {
        float* orow = out + (size_t)n * DIMF;
        float x0 = (as[0] - mu) * rstd * gl.x + bl.x;
        float x1 = (as[1] - mu) * rstd * gl.y + bl.y;
        float x2 = (as[2] - mu) * rstd * gl.z + bl.z;
        float x3 = (as[3] - mu) * rstd * gl.w + bl.w;
        float4 r0 = make_float4(x0 / (1.f + expf(-x0)), x1 / (1.f + expf(-x1)),
                                x2 / (1.f + expf(-x2)), x3 / (1.f + expf(-x3)));
        float y0 = (as[4] - mu) * rstd * gh.x + bh.x;
        float y1 = (as[5] - mu) * rstd * gh.y + bh.y;
        float y2 = (as[6] - mu) * rstd * gh.z + bh.z;
        float y3 = (as[7] - mu) * rstd * gh.w + bh.w;
        float4 r1 = make_float4(y0 / (1.f + expf(-y0)), y1 / (1.f + expf(-y1)),
                                y2 / (1.f + expf(-y2)), y3 / (1.f + expf(-y3)));
        *reinterpret_cast<float4*>(orow + tc * 4)      = r0;
        *reinterpret_cast<float4*>(orow + 32 + tc * 4) = r1;
        float* ov = orow + SC + tc * 12;
        *reinterpret_cast<float4*>(ov + 0) =
            make_float4(avv[0] * ewv, avv[1] * ewv, avv[2] * ewv, avv[3] * ewv);
        *reinterpret_cast<float4*>(ov + 4) =
            make_float4(avv[4] * ewv, avv[5] * ewv, avv[6] * ewv, avv[7] * ewv);
        *reinterpret_cast<float4*>(ov + 8) =
            make_float4(avv[8] * ewv, avv[9] * ewv, avv[10] * ewv, avv[11] * ewv);
    }
}

extern "C" void kernel_launch(void* const* d_in, const int* in_sizes, int n_in,
                              void* d_out, int out_size) {
    const float* x       = (const float*)d_in[0];
    const float* pos     = (const float*)d_in[1];
    const int*   ei      = (const int*)d_in[2];   // int32 (JAX x64 disabled)
    // d_in[3] = edge_rand: unused (rotation cancels algebraically)
    const float* W0      = (const float*)d_in[4];
    const float* W1      = (const float*)d_in[5];
    const float* centers = (const float*)d_in[6];
    const float* widths  = (const float*)d_in[7];
    const float* pw      = (const float*)d_in[8];
    const float* pb      = (const float*)d_in[9];
    const float* gamma   = (const float*)d_in[10];
    const float* beta    = (const float*)d_in[11];
    float* out = (float*)d_out;

    int N = in_sizes[0] / DIMF;
    int E = in_sizes[2] / 2;
    int nq = (N * DIMF) / 4;   // float4 count of out

    // Wide grid: zeroing at memset parallelism; table lives in first 512 blocks.
    k_table_zero<<<2560, 256>>>(centers, widths, pw, pb, (float4*)out, nq);
    k_scatter<<<(E + 31) / 32, 256>>>(ei, x, pos, out, E);
    k_finalize<<<(N + TILE_N - 1) / TILE_N, 256>>>(out, W0, W1, gamma, beta, N, E);
}